// round 9
// baseline (speedup 1.0000x reference)
#include <cuda_runtime.h>
#include <cuda_bf16.h>
#include <cstdint>

#define B_ 256
#define L_ 4096
#define H_ 64
#define V_ 64

__device__ float g_K[V_ * H_];
__device__ float g_invd[V_];

// ---------------------------------------------------------------------------
// Phase 1: vocab table (V==64 collapses embed+FF+LN to a 64x64 LUT)
// ---------------------------------------------------------------------------
__global__ void build_table_kernel(const float* __restrict__ embed_W,
                                   const float* __restrict__ w1,
                                   const float* __restrict__ b1,
                                   const float* __restrict__ w2,
                                   const float* __restrict__ b2,
                                   const float* __restrict__ lnw,
                                   const float* __restrict__ lnb)
{
    __shared__ float e[H_], a[2 * H_], hrow[H_], red[H_];
    const int v = blockIdx.x, t = threadIdx.x;

    e[t] = embed_W[v * H_ + t];
    __syncthreads();

    float a0 = b1[t], a1 = b1[t + H_];
    #pragma unroll 8
    for (int k = 0; k < H_; k++) {
        float ek = e[k];
        a0 += ek * w1[k * 2 * H_ + t];
        a1 += ek * w1[k * 2 * H_ + t + H_];
    }
    a[t] = fmaxf(a0, 0.f); a[t + H_] = fmaxf(a1, 0.f);
    __syncthreads();

    float f = b2[t];
    #pragma unroll 8
    for (int o = 0; o < 2 * H_; o++) f += a[o] * w2[o * H_ + t];
    hrow[t] = e[t] + f;
    __syncthreads();

    float mu = 0.f;
    #pragma unroll 8
    for (int j = 0; j < H_; j++) mu += hrow[j];
    mu *= (1.f / H_);
    float var = 0.f;
    #pragma unroll 8
    for (int j = 0; j < H_; j++) { float d = hrow[j] - mu; var += d * d; }
    var *= (1.f / H_);

    float kv = (hrow[t] - mu) * rsqrtf(var + 1e-5f) * lnw[t] + lnb[t];
    g_K[v * H_ + t] = kv;
    red[t] = kv * kv;
    __syncthreads();
    if (t == 0) {
        float d = 0.f;
        #pragma unroll 8
        for (int j = 0; j < H_; j++) d += red[j];
        g_invd[v] = 1.f / (d + 1e-6f);
    }
}

// ---------------------------------------------------------------------------
// bf16 mma.sync m16n8k16 (valid on plain compute_103)
// ---------------------------------------------------------------------------
__device__ __forceinline__ void mma_bf16(float d[4], const uint32_t a[4],
                                         const uint32_t b[2])
{
    asm volatile("mma.sync.aligned.m16n8k16.row.col.f32.bf16.bf16.f32 "
                 "{%0,%1,%2,%3}, {%4,%5,%6,%7}, {%8,%9}, {%0,%1,%2,%3};"
                 : "+f"(d[0]), "+f"(d[1]), "+f"(d[2]), "+f"(d[3])
                 : "r"(a[0]), "r"(a[1]), "r"(a[2]), "r"(a[3]),
                   "r"(b[0]), "r"(b[1]));
}

// ---------------------------------------------------------------------------
// Shared layout (float offsets); 4 batch-groups per block
// ---------------------------------------------------------------------------
#define CSTR 72
#define PST  72
#define NG   4
#define OFF_GF   0          // exact G 64x64 fp32
#define OFF_GP   4096       // packed u32: bf16 hi | lo<<16
#define OFF_CROW 8192       // NG x 64 x CSTR (exported C rows)
#define OFF_AP   26624      // NG x [2sp][8 pairs][PST] u32
#define OFF_BP   31232      // same
#define OFF_KSH  35840      // K table 64x64
#define OFF_INVD 39936
#define OFF_TOK  40000      // int [2 buf][NG group][16]
#define OFF_XCH  40128      // 256
#define SMEM_FLOATS 40384   // 161536 bytes

// ---------------------------------------------------------------------------
// One chunk of T (<=16) delta-rule steps for one 64-thread batch-group.
// C state lives in MMA register fragments D; only rows needed by the NEXT
// chunk's beta-gather are exported to shared.
// ---------------------------------------------------------------------------
template<int T, bool TAIL, bool FIRST>
__device__ __forceinline__ void chunk(float* sm, int h, int w, int lane, int wg,
                                      int buf, int nb, float (&D)[4][4][4])
{
    const int*      tok  = (const int*)(sm + OFF_TOK) + buf * (NG * 16) + h * 16;
    const float*    Gf   = sm + OFF_GF;
    const uint32_t* Gp   = (const uint32_t*)(sm + OFF_GP);
    const float*    invd = sm + OFF_INVD;
    float*    Crow = sm + OFF_CROW + h * 64 * CSTR;
    uint32_t* Ap   = (uint32_t*)(sm + OFF_AP) + h * 16 * PST;
    uint32_t* Bp   = (uint32_t*)(sm + OFF_BP) + h * 16 * PST;

    int s[16];
    #pragma unroll
    for (int j = 0; j < 16; j++) s[j] = tok[j];

    // beta bases (C at chunk start) from exported rows
    float pend[16];
    #pragma unroll
    for (int j = 0; j < 16; j++)
        pend[j] = (!FIRST && j < T) ? Crow[s[j] * CSTR + w] : 0.f;

    // exact serial alpha chain with forward fan-out corrections
    float alpha[16];
    #pragma unroll
    for (int u = 0; u < 16; u++) {
        if (u < T) {
            const float e = (w == s[u]) ? 1.f : 0.f;
            alpha[u] = fmaf(-invd[s[u]], pend[u], e);
            #pragma unroll
            for (int j = u + 1; j < 16; j++)
                if (j < T)
                    pend[j] = fmaf(Gf[s[u] * 64 + s[j]], alpha[u], pend[j]);
        } else alpha[u] = 0.f;
    }

    // stage B = alpha (hi/lo bf16 split), pair-major: Bp[sp*8+p][w]
    #pragma unroll
    for (int p = 0; p < 8; p++) {
        const float x0 = alpha[2 * p], x1 = alpha[2 * p + 1];
        const __nv_bfloat16 h0 = __float2bfloat16(x0), h1 = __float2bfloat16(x1);
        const float l0 = x0 - __bfloat162float(h0), l1 = x1 - __bfloat162float(h1);
        const __nv_bfloat16 c0 = __float2bfloat16(l0), c1 = __float2bfloat16(l1);
        Bp[p * PST + w]       = (uint32_t)__bfloat16_as_ushort(h0)
                              | ((uint32_t)__bfloat16_as_ushort(h1) << 16);
        Bp[(8 + p) * PST + w] = (uint32_t)__bfloat16_as_ushort(c0)
                              | ((uint32_t)__bfloat16_as_ushort(c1) << 16);
    }
    // stage A = Gsel^T from packed table: Ap[sp*8+p][x=w]
    #pragma unroll
    for (int p = 0; p < 8; p++) {
        const uint32_t q0 = Gp[s[2 * p] * 64 + w];
        const uint32_t q1 = Gp[s[2 * p + 1] * 64 + w];
        Ap[p * PST + w]       = (q0 & 0xFFFFu) | (q1 << 16);
        Ap[(8 + p) * PST + w] = (q0 >> 16) | (q1 & 0xFFFF0000u);
    }

    asm volatile("bar.sync %0, 64;" :: "r"(h + 1) : "memory");

    // rows needed by the next chunk
    uint64_t mask;
    if (TAIL) {
        mask = 1ull << s[15];
    } else {
        const int* ntok = (const int*)(sm + OFF_TOK) + nb * (NG * 16) + h * 16;
        mask = 0;
        #pragma unroll
        for (int j = 0; j < 16; j++) mask |= (1ull << ntok[j]);
    }

    const int gid = lane >> 2, tig = lane & 3;

    uint32_t Ahf[4][4], Alf[4][4];
    #pragma unroll
    for (int mi = 0; mi < 4; mi++) {
        const int r0 = mi * 16 + gid;
        Ahf[mi][0] = Ap[tig * PST + r0];          Ahf[mi][1] = Ap[tig * PST + r0 + 8];
        Ahf[mi][2] = Ap[(tig + 4) * PST + r0];    Ahf[mi][3] = Ap[(tig + 4) * PST + r0 + 8];
        Alf[mi][0] = Ap[(8 + tig) * PST + r0];    Alf[mi][1] = Ap[(8 + tig) * PST + r0 + 8];
        Alf[mi][2] = Ap[(12 + tig) * PST + r0];   Alf[mi][3] = Ap[(12 + tig) * PST + r0 + 8];
    }
    uint32_t Bhf[4][2], Blf[4][2];
    #pragma unroll
    for (int nl = 0; nl < 4; nl++) {
        const int nc = wg * 32 + nl * 8 + gid;
        Bhf[nl][0] = Bp[tig * PST + nc];       Bhf[nl][1] = Bp[(tig + 4) * PST + nc];
        Blf[nl][0] = Bp[(8 + tig) * PST + nc]; Blf[nl][1] = Bp[(12 + tig) * PST + nc];
    }

    #pragma unroll
    for (int mi = 0; mi < 4; mi++)
        #pragma unroll
        for (int nl = 0; nl < 4; nl++) {
            mma_bf16(D[mi][nl], Ahf[mi], Bhf[nl]);   // hh
            mma_bf16(D[mi][nl], Alf[mi], Bhf[nl]);   // lh
            mma_bf16(D[mi][nl], Ahf[mi], Blf[nl]);   // hl
        }

    // export owned rows hit by the mask
    #pragma unroll
    for (int mi = 0; mi < 4; mi++) {
        #pragma unroll
        for (int hr = 0; hr < 2; hr++) {
            const int r = mi * 16 + hr * 8 + gid;
            if ((mask >> r) & 1ull) {
                #pragma unroll
                for (int nl = 0; nl < 4; nl++) {
                    const int cb = wg * 32 + nl * 8 + tig * 2;
                    *(float2*)&Crow[r * CSTR + cb] =
                        make_float2(D[mi][nl][2 * hr], D[mi][nl][2 * hr + 1]);
                }
            }
        }
    }
    asm volatile("bar.sync %0, 64;" :: "r"(h + 1) : "memory");
}

// ---------------------------------------------------------------------------
// Phase 2+3: register-resident coefficient scan + readout.
// grid 64 x block 256 (4 independent 64-thread batch-groups -> 2 warps/SMSP).
// ---------------------------------------------------------------------------
extern __shared__ float s_dyn[];

__global__ __launch_bounds__(256, 1)
void scan_kernel(const int* __restrict__ seq,
                 const float* __restrict__ read_w,
                 const float* __restrict__ read_b,
                 const float* __restrict__ out_w,
                 const float* __restrict__ out_b,
                 float* __restrict__ out)
{
    float* sm = s_dyn;
    const int tid  = threadIdx.x;
    const int lane = tid & 31;
    const int h    = tid >> 6;          // batch-group 0..3
    const int w    = tid & 63;          // owned column
    const int wg   = (tid >> 5) & 1;    // warp within group
    const int b0   = blockIdx.x * NG;
    const int ldr  = (w < 16);          // token-loader lanes of each group

    // ---- prologue: K, invd, tokens, Gram (fused), packed G ----
    float4* Ksh4 = (float4*)(sm + OFF_KSH);
    for (int i = tid; i < V_ * H_ / 4; i += 256)
        Ksh4[i] = reinterpret_cast<const float4*>(g_K)[i];
    if (tid < V_) sm[OFF_INVD + tid] = g_invd[tid];
    int* tokb = (int*)(sm + OFF_TOK);
    if (ldr) tokb[h * 16 + w] = __ldg(seq + (long)(b0 + h) * L_ + w);
    __syncthreads();

    {   // Gram: thread t computes row t>>2, 16 columns
        const int r = tid >> 2, ch = (tid & 3) * 16;
        float4 krow[16];
        #pragma unroll
        for (int i = 0; i < 16; i++) krow[i] = Ksh4[r * 16 + i];
        for (int c = ch; c < ch + 16; c++) {
            float a0 = 0.f, a1 = 0.f, a2 = 0.f, a3 = 0.f;
            #pragma unroll
            for (int i = 0; i < 16; i++) {
                const float4 kc = Ksh4[c * 16 + i];
                a0 = fmaf(krow[i].x, kc.x, a0);
                a1 = fmaf(krow[i].y, kc.y, a1);
                a2 = fmaf(krow[i].z, kc.z, a2);
                a3 = fmaf(krow[i].w, kc.w, a3);
            }
            sm[OFF_GF + r * 64 + c] = (a0 + a1) + (a2 + a3);
        }
    }
    __syncthreads();
    {   // packed bf16 hi|lo split of G
        uint32_t* Gp = (uint32_t*)(sm + OFF_GP);
        for (int i = tid; i < V_ * V_; i += 256) {
            const float g = sm[OFF_GF + i];
            const __nv_bfloat16 hi = __float2bfloat16(g);
            const __nv_bfloat16 lo = __float2bfloat16(g - __bfloat162float(hi));
            Gp[i] = (uint32_t)__bfloat16_as_ushort(hi)
                  | ((uint32_t)__bfloat16_as_ushort(lo) << 16);
        }
    }
    __syncthreads();

    float D[4][4][4];
    #pragma unroll
    for (int a = 0; a < 4; a++)
        #pragma unroll
        for (int b = 0; b < 4; b++)
            #pragma unroll
            for (int c = 0; c < 4; c++) D[a][b][c] = 0.f;

    // ---- chunk 0 ----
    if (ldr) tokb[NG * 16 + h * 16 + w] = __ldg(seq + (long)(b0 + h) * L_ + 16 + w);
    chunk<16, false, true>(sm, h, w, lane, wg, 0, 1, D);

    // ---- chunks 1..254 ----
    #pragma unroll 1
    for (int c = 1; c < 255; c++) {
        const int nb = (c + 1) & 1;
        if (ldr)
            tokb[nb * (NG * 16) + h * 16 + w] =
                __ldg(seq + (long)(b0 + h) * L_ + (c + 1) * 16 + w);
        chunk<16, false, false>(sm, h, w, lane, wg, c & 1, nb, D);
    }
    // ---- tail: steps 4080..4094, slot 15 = query ----
    chunk<15, true, false>(sm, h, w, lane, wg, 1, 0, D);

    __syncthreads();

    // ---- epilogue ----
    float* xch = sm + OFF_XCH;
    const int sq = ((const int*)(sm + OFF_TOK))[NG * 16 + h * 16 + 15];
    xch[tid] = (sm + OFF_CROW + h * 64 * CSTR)[sq * CSTR + w];
    __syncthreads();

    float ctx = 0.f;
    #pragma unroll 8
    for (int v = 0; v < V_; v++)
        ctx = fmaf(xch[(h << 6) + v], sm[OFF_KSH + v * 64 + w], ctx);
    __syncthreads(); xch[tid] = ctx; __syncthreads();

    float r = read_b[w];
    #pragma unroll 8
    for (int j = 0; j < H_; j++) r = fmaf(xch[(h << 6) + j], read_w[j * H_ + w], r);
    __syncthreads(); xch[tid] = r; __syncthreads();

    float o = out_b[w];
    #pragma unroll 8
    for (int j = 0; j < H_; j++) o = fmaf(xch[(h << 6) + j], out_w[j * V_ + w], o);
    out[(b0 + h) * V_ + w] = o;
}

// ---------------------------------------------------------------------------
extern "C" void kernel_launch(void* const* d_in, const int* in_sizes, int n_in,
                              void* d_out, int out_size)
{
    const int*   seq     = (const int*)  d_in[0];
    const float* embed_W = (const float*)d_in[1];
    const float* ff_w1   = (const float*)d_in[2];
    const float* ff_b1   = (const float*)d_in[3];
    const float* ff_w2   = (const float*)d_in[4];
    const float* ff_b2   = (const float*)d_in[5];
    const float* ln_w    = (const float*)d_in[6];
    const float* ln_b    = (const float*)d_in[7];
    const float* read_w  = (const float*)d_in[8];
    const float* read_b  = (const float*)d_in[9];
    const float* out_w   = (const float*)d_in[10];
    const float* out_b   = (const float*)d_in[11];
    float* out = (float*)d_out;

    const int smem_bytes = SMEM_FLOATS * 4;
    cudaFuncSetAttribute(scan_kernel,
                         cudaFuncAttributeMaxDynamicSharedMemorySize, smem_bytes);

    build_table_kernel<<<V_, H_>>>(embed_W, ff_w1, ff_b1, ff_w2, ff_b2,
                                   ln_w, ln_b);
    scan_kernel<<<B_ / NG, 256, smem_bytes>>>(seq, read_w, read_b,
                                              out_w, out_b, out);
}

// round 10
// speedup vs baseline: 1.6263x; 1.6263x over previous
#include <cuda_runtime.h>
#include <cuda_bf16.h>
#include <cstdint>

#define B_ 256
#define L_ 4096
#define H_ 64
#define V_ 64

__device__ float g_K[V_ * H_];
__device__ float g_invd[V_];

// ---------------------------------------------------------------------------
// Phase 1: vocab table (V==64 collapses embed+FF+LN to a 64x64 LUT)
// ---------------------------------------------------------------------------
__global__ void build_table_kernel(const float* __restrict__ embed_W,
                                   const float* __restrict__ w1,
                                   const float* __restrict__ b1,
                                   const float* __restrict__ w2,
                                   const float* __restrict__ b2,
                                   const float* __restrict__ lnw,
                                   const float* __restrict__ lnb)
{
    __shared__ float e[H_], a[2 * H_], hrow[H_], red[H_];
    const int v = blockIdx.x, t = threadIdx.x;

    e[t] = embed_W[v * H_ + t];
    __syncthreads();

    float a0 = b1[t], a1 = b1[t + H_];
    #pragma unroll 8
    for (int k = 0; k < H_; k++) {
        float ek = e[k];
        a0 += ek * w1[k * 2 * H_ + t];
        a1 += ek * w1[k * 2 * H_ + t + H_];
    }
    a[t] = fmaxf(a0, 0.f); a[t + H_] = fmaxf(a1, 0.f);
    __syncthreads();

    float f = b2[t];
    #pragma unroll 8
    for (int o = 0; o < 2 * H_; o++) f += a[o] * w2[o * H_ + t];
    hrow[t] = e[t] + f;
    __syncthreads();

    float mu = 0.f;
    #pragma unroll 8
    for (int j = 0; j < H_; j++) mu += hrow[j];
    mu *= (1.f / H_);
    float var = 0.f;
    #pragma unroll 8
    for (int j = 0; j < H_; j++) { float d = hrow[j] - mu; var += d * d; }
    var *= (1.f / H_);

    float kv = (hrow[t] - mu) * rsqrtf(var + 1e-5f) * lnw[t] + lnb[t];
    g_K[v * H_ + t] = kv;
    red[t] = kv * kv;
    __syncthreads();
    if (t == 0) {
        float d = 0.f;
        #pragma unroll 8
        for (int j = 0; j < H_; j++) d += red[j];
        g_invd[v] = 1.f / (d + 1e-6f);
    }
}

// ---------------------------------------------------------------------------
// bf16 mma.sync m16n8k16 (valid on plain compute_103)
// ---------------------------------------------------------------------------
__device__ __forceinline__ void mma_bf16(float d[4], const uint32_t a[4],
                                         const uint32_t b[2])
{
    asm volatile("mma.sync.aligned.m16n8k16.row.col.f32.bf16.bf16.f32 "
                 "{%0,%1,%2,%3}, {%4,%5,%6,%7}, {%8,%9}, {%0,%1,%2,%3};"
                 : "+f"(d[0]), "+f"(d[1]), "+f"(d[2]), "+f"(d[3])
                 : "r"(a[0]), "r"(a[1]), "r"(a[2]), "r"(a[3]),
                   "r"(b[0]), "r"(b[1]));
}

// ---------------------------------------------------------------------------
// Shared layout (float offsets)
// ---------------------------------------------------------------------------
#define CSTR  72
#define PST   72
#define GPSTR 66            // padded G row stride (bank-conflict avoidance)
#define OFF_GF   0          // exact G 64x64 fp32                       4096
#define OFF_GP   4096       // packed u32 bf16 hi|lo<<16, stride 66     4224
#define OFF_CROW 8320       // 2 groups x 64 x CSTR                     9216
#define OFF_BP   17536      // 2 groups x 16 x PST                      2304
#define OFF_KSH  19840      // K table                                  4096
#define OFF_INVD 23936      // 64
#define OFF_TOK  24000      // int [2 buf][4 warp][16]                   128
#define OFF_XCH  24128      // 128
#define SMEM_FLOATS 24256   // 97024 bytes

// ---------------------------------------------------------------------------
// One chunk of T (<=16) delta-rule steps for one WARP (owns 32 N-columns of
// one batch's C).  Barrier-free: only __syncwarp().
// ---------------------------------------------------------------------------
template<int T, bool TAIL, bool FIRST>
__device__ __forceinline__ void chunk(float* sm, const int* __restrict__ spq,
                                      int h, int gw, int w, int lane, int wg,
                                      int buf, int nb, int cnext,
                                      float (&D)[4][4][4])
{
    const float*    Gf   = sm + OFF_GF;
    const uint32_t* Gp   = (const uint32_t*)(sm + OFF_GP);
    const float*    invd = sm + OFF_INVD;
    float* Crow = sm + OFF_CROW + h * 64 * CSTR;
    float* Bp   = sm + OFF_BP   + h * 16 * PST;
    int*   tokw = (int*)(sm + OFF_TOK);

    const int gid = lane >> 2, tig = lane & 3;

    // tokens for this chunk (broadcast LDS, warp-own buffer)
    int s[16];
    #pragma unroll
    for (int j = 0; j < 16; j++) s[j] = tokw[buf * 64 + gw * 16 + j];

    // beta bases (C at chunk start) — own column of exported rows
    float pend[16];
    #pragma unroll
    for (int j = 0; j < 16; j++)
        pend[j] = (!FIRST && j < T) ? Crow[s[j] * CSTR + w] : 0.f;

    // A fragments: direct gather from packed G (token-only dependent; the
    // LDS latency overlaps the alpha chain below)
    uint32_t Ahf[4][4], Alf[4][4];
    #pragma unroll
    for (int mi = 0; mi < 4; mi++) {
        const int r0 = mi * 16 + gid;
        const uint32_t q0 = Gp[s[2 * tig]     * GPSTR + r0];
        const uint32_t q1 = Gp[s[2 * tig + 1] * GPSTR + r0];
        const uint32_t q2 = Gp[s[2 * tig]     * GPSTR + r0 + 8];
        const uint32_t q3 = Gp[s[2 * tig + 1] * GPSTR + r0 + 8];
        const uint32_t q4 = Gp[s[2 * tig + 8] * GPSTR + r0];
        const uint32_t q5 = Gp[s[2 * tig + 9] * GPSTR + r0];
        const uint32_t q6 = Gp[s[2 * tig + 8] * GPSTR + r0 + 8];
        const uint32_t q7 = Gp[s[2 * tig + 9] * GPSTR + r0 + 8];
        Ahf[mi][0] = (q0 & 0xFFFFu) | (q1 << 16);
        Alf[mi][0] = (q0 >> 16) | (q1 & 0xFFFF0000u);
        Ahf[mi][1] = (q2 & 0xFFFFu) | (q3 << 16);
        Alf[mi][1] = (q2 >> 16) | (q3 & 0xFFFF0000u);
        Ahf[mi][2] = (q4 & 0xFFFFu) | (q5 << 16);
        Alf[mi][2] = (q4 >> 16) | (q5 & 0xFFFF0000u);
        Ahf[mi][3] = (q6 & 0xFFFFu) | (q7 << 16);
        Alf[mi][3] = (q6 >> 16) | (q7 & 0xFFFF0000u);
    }

    // prefetch next chunk's tokens (own warp's buffer)
    if (!TAIL && lane < 16)
        tokw[nb * 64 + gw * 16 + lane] = __ldg(spq + cnext * 16 + lane);

    // exact serial alpha chain with forward fan-out corrections
    float alpha[16];
    #pragma unroll
    for (int u = 0; u < 16; u++) {
        if (u < T) {
            const float e = (w == s[u]) ? 1.f : 0.f;
            alpha[u] = fmaf(-invd[s[u]], pend[u], e);
            #pragma unroll
            for (int j = u + 1; j < 16; j++)
                if (j < T)
                    pend[j] = fmaf(Gf[s[u] * 64 + s[j]], alpha[u], pend[j]);
        } else alpha[u] = 0.f;
    }

    // stage B = alpha (hi/lo bf16 split), own column only
    #pragma unroll
    for (int p = 0; p < 8; p++) {
        const float x0 = alpha[2 * p], x1 = alpha[2 * p + 1];
        const __nv_bfloat16 h0 = __float2bfloat16(x0), h1 = __float2bfloat16(x1);
        const float l0 = x0 - __bfloat162float(h0), l1 = x1 - __bfloat162float(h1);
        const __nv_bfloat16 c0 = __float2bfloat16(l0), c1 = __float2bfloat16(l1);
        Bp[p * PST + w]       = __uint_as_float((uint32_t)__bfloat16_as_ushort(h0)
                              | ((uint32_t)__bfloat16_as_ushort(h1) << 16));
        Bp[(8 + p) * PST + w] = __uint_as_float((uint32_t)__bfloat16_as_ushort(c0)
                              | ((uint32_t)__bfloat16_as_ushort(c1) << 16));
    }

    __syncwarp();

    // rows needed by the next chunk's gather
    uint64_t mask;
    if (TAIL) {
        mask = 1ull << s[15];
    } else {
        mask = 0;
        #pragma unroll
        for (int j = 0; j < 16; j++)
            mask |= (1ull << tokw[nb * 64 + gw * 16 + j]);
    }

    // B fragments (own warp's columns)
    uint32_t Bhf[4][2], Blf[4][2];
    #pragma unroll
    for (int nl = 0; nl < 4; nl++) {
        const int nc = wg * 32 + nl * 8 + gid;
        Bhf[nl][0] = __float_as_uint(Bp[tig * PST + nc]);
        Bhf[nl][1] = __float_as_uint(Bp[(tig + 4) * PST + nc]);
        Blf[nl][0] = __float_as_uint(Bp[(8 + tig) * PST + nc]);
        Blf[nl][1] = __float_as_uint(Bp[(12 + tig) * PST + nc]);
    }

    #pragma unroll
    for (int mi = 0; mi < 4; mi++)
        #pragma unroll
        for (int nl = 0; nl < 4; nl++) {
            mma_bf16(D[mi][nl], Ahf[mi], Bhf[nl]);   // hh
            mma_bf16(D[mi][nl], Alf[mi], Bhf[nl]);   // lh
            mma_bf16(D[mi][nl], Ahf[mi], Blf[nl]);   // hl
        }

    // export owned rows hit by the mask (own warp's columns)
    #pragma unroll
    for (int mi = 0; mi < 4; mi++) {
        #pragma unroll
        for (int hr = 0; hr < 2; hr++) {
            const int r = mi * 16 + hr * 8 + gid;
            if ((mask >> r) & 1ull) {
                #pragma unroll
                for (int nl = 0; nl < 4; nl++) {
                    const int cb = wg * 32 + nl * 8 + tig * 2;
                    *(float2*)&Crow[r * CSTR + cb] =
                        make_float2(D[mi][nl][2 * hr], D[mi][nl][2 * hr + 1]);
                }
            }
        }
    }
    __syncwarp();
}

// ---------------------------------------------------------------------------
// Phase 2+3: register-resident coefficient scan + readout.
// grid 128 x block 128; each of the 4 warps is a fully independent stream
// owning 32 N-columns of one batch's C.
// ---------------------------------------------------------------------------
extern __shared__ float s_dyn[];

__global__ __launch_bounds__(128, 1)
void scan_kernel(const int* __restrict__ seq,
                 const float* __restrict__ read_w,
                 const float* __restrict__ read_b,
                 const float* __restrict__ out_w,
                 const float* __restrict__ out_b,
                 float* __restrict__ out)
{
    float* sm = s_dyn;
    const int tid  = threadIdx.x;
    const int lane = tid & 31;
    const int gw   = tid >> 5;          // warp in block 0..3
    const int h    = gw >> 1;           // batch-group
    const int wg   = gw & 1;            // N-half
    const int w    = tid & 63;          // owned column
    const int b0   = blockIdx.x * 2;
    const int* spq = seq + (long)(b0 + h) * L_;

    // ---- prologue: K, invd, tokens, Gram, packed G ----
    float4* Ksh4 = (float4*)(sm + OFF_KSH);
    for (int i = tid; i < V_ * H_ / 4; i += 128)
        Ksh4[i] = reinterpret_cast<const float4*>(g_K)[i];
    if (tid < V_) sm[OFF_INVD + tid] = g_invd[tid];
    int* tokw = (int*)(sm + OFF_TOK);
    if (lane < 16) tokw[gw * 16 + lane] = __ldg(spq + lane);
    __syncthreads();

    {   // Gram: thread t computes row t>>1, 32 columns
        const int r = tid >> 1, ch = (tid & 1) * 32;
        float4 krow[16];
        #pragma unroll
        for (int i = 0; i < 16; i++) krow[i] = Ksh4[r * 16 + i];
        for (int c = ch; c < ch + 32; c++) {
            float a0 = 0.f, a1 = 0.f, a2 = 0.f, a3 = 0.f;
            #pragma unroll
            for (int i = 0; i < 16; i++) {
                const float4 kc = Ksh4[c * 16 + i];
                a0 = fmaf(krow[i].x, kc.x, a0);
                a1 = fmaf(krow[i].y, kc.y, a1);
                a2 = fmaf(krow[i].z, kc.z, a2);
                a3 = fmaf(krow[i].w, kc.w, a3);
            }
            sm[OFF_GF + r * 64 + c] = (a0 + a1) + (a2 + a3);
        }
    }
    __syncthreads();
    {   // packed bf16 hi|lo split of G, padded stride
        uint32_t* Gp = (uint32_t*)(sm + OFF_GP);
        for (int i = tid; i < V_ * V_; i += 128) {
            const int r = i >> 6, c = i & 63;
            const float g = sm[OFF_GF + i];
            const __nv_bfloat16 hi = __float2bfloat16(g);
            const __nv_bfloat16 lo = __float2bfloat16(g - __bfloat162float(hi));
            Gp[r * GPSTR + c] = (uint32_t)__bfloat16_as_ushort(hi)
                              | ((uint32_t)__bfloat16_as_ushort(lo) << 16);
        }
    }
    __syncthreads();

    float D[4][4][4];
    #pragma unroll
    for (int a = 0; a < 4; a++)
        #pragma unroll
        for (int b = 0; b < 4; b++)
            #pragma unroll
            for (int c = 0; c < 4; c++) D[a][b][c] = 0.f;

    // ---- chunk 0, then 1..254, then tail ----
    chunk<16, false, true>(sm, spq, h, gw, w, lane, wg, 0, 1, 1, D);
    #pragma unroll 1
    for (int c = 1; c < 255; c++)
        chunk<16, false, false>(sm, spq, h, gw, w, lane, wg,
                                c & 1, (c + 1) & 1, c + 1, D);
    chunk<15, true, false>(sm, spq, h, gw, w, lane, wg, 1, 0, 0, D);

    __syncthreads();

    // ---- epilogue ----
    float* xch = sm + OFF_XCH;
    const int sq = ((const int*)(sm + OFF_TOK))[64 + gw * 16 + 15];
    xch[tid] = (sm + OFF_CROW + h * 64 * CSTR)[sq * CSTR + w];
    __syncthreads();

    float ctx = 0.f;
    #pragma unroll 8
    for (int v = 0; v < V_; v++)
        ctx = fmaf(xch[(h << 6) + v], sm[OFF_KSH + v * 64 + w], ctx);
    __syncthreads(); xch[tid] = ctx; __syncthreads();

    float r = read_b[w];
    #pragma unroll 8
    for (int j = 0; j < H_; j++) r = fmaf(xch[(h << 6) + j], read_w[j * H_ + w], r);
    __syncthreads(); xch[tid] = r; __syncthreads();

    float o = out_b[w];
    #pragma unroll 8
    for (int j = 0; j < H_; j++) o = fmaf(xch[(h << 6) + j], out_w[j * V_ + w], o);
    out[(b0 + h) * V_ + w] = o;
}

// ---------------------------------------------------------------------------
extern "C" void kernel_launch(void* const* d_in, const int* in_sizes, int n_in,
                              void* d_out, int out_size)
{
    const int*   seq     = (const int*)  d_in[0];
    const float* embed_W = (const float*)d_in[1];
    const float* ff_w1   = (const float*)d_in[2];
    const float* ff_b1   = (const float*)d_in[3];
    const float* ff_w2   = (const float*)d_in[4];
    const float* ff_b2   = (const float*)d_in[5];
    const float* ln_w    = (const float*)d_in[6];
    const float* ln_b    = (const float*)d_in[7];
    const float* read_w  = (const float*)d_in[8];
    const float* read_b  = (const float*)d_in[9];
    const float* out_w   = (const float*)d_in[10];
    const float* out_b   = (const float*)d_in[11];
    float* out = (float*)d_out;

    const int smem_bytes = SMEM_FLOATS * 4;
    cudaFuncSetAttribute(scan_kernel,
                         cudaFuncAttributeMaxDynamicSharedMemorySize, smem_bytes);

    build_table_kernel<<<V_, H_>>>(embed_W, ff_w1, ff_b1, ff_w2, ff_b2,
                                   ln_w, ln_b);
    scan_kernel<<<B_ / 2, 128, smem_bytes>>>(seq, read_w, read_b,
                                             out_w, out_b, out);
}

// round 11
// speedup vs baseline: 1.9008x; 1.1688x over previous
#include <cuda_runtime.h>
#include <cuda_bf16.h>
#include <cstdint>

#define B_ 256
#define L_ 4096
#define H_ 64
#define V_ 64

__device__ float g_K[V_ * H_];
__device__ float g_invd[V_];

// ---------------------------------------------------------------------------
// Phase 1: vocab table (V==64 collapses embed+FF+LN to a 64x64 LUT)
// ---------------------------------------------------------------------------
__global__ void build_table_kernel(const float* __restrict__ embed_W,
                                   const float* __restrict__ w1,
                                   const float* __restrict__ b1,
                                   const float* __restrict__ w2,
                                   const float* __restrict__ b2,
                                   const float* __restrict__ lnw,
                                   const float* __restrict__ lnb)
{
    __shared__ float e[H_], a[2 * H_], hrow[H_], red[H_];
    const int v = blockIdx.x, t = threadIdx.x;

    e[t] = embed_W[v * H_ + t];
    __syncthreads();

    float a0 = b1[t], a1 = b1[t + H_];
    #pragma unroll 8
    for (int k = 0; k < H_; k++) {
        float ek = e[k];
        a0 += ek * w1[k * 2 * H_ + t];
        a1 += ek * w1[k * 2 * H_ + t + H_];
    }
    a[t] = fmaxf(a0, 0.f); a[t + H_] = fmaxf(a1, 0.f);
    __syncthreads();

    float f = b2[t];
    #pragma unroll 8
    for (int o = 0; o < 2 * H_; o++) f += a[o] * w2[o * H_ + t];
    hrow[t] = e[t] + f;
    __syncthreads();

    float mu = 0.f;
    #pragma unroll 8
    for (int j = 0; j < H_; j++) mu += hrow[j];
    mu *= (1.f / H_);
    float var = 0.f;
    #pragma unroll 8
    for (int j = 0; j < H_; j++) { float d = hrow[j] - mu; var += d * d; }
    var *= (1.f / H_);

    float kv = (hrow[t] - mu) * rsqrtf(var + 1e-5f) * lnw[t] + lnb[t];
    g_K[v * H_ + t] = kv;
    red[t] = kv * kv;
    __syncthreads();
    if (t == 0) {
        float d = 0.f;
        #pragma unroll 8
        for (int j = 0; j < H_; j++) d += red[j];
        g_invd[v] = 1.f / (d + 1e-6f);
    }
}

// ---------------------------------------------------------------------------
// bf16 mma.sync m16n8k16 (valid on plain compute_103)
// ---------------------------------------------------------------------------
__device__ __forceinline__ void mma_bf16(float d[4], const uint32_t a[4],
                                         const uint32_t b[2])
{
    asm volatile("mma.sync.aligned.m16n8k16.row.col.f32.bf16.bf16.f32 "
                 "{%0,%1,%2,%3}, {%4,%5,%6,%7}, {%8,%9}, {%0,%1,%2,%3};"
                 : "+f"(d[0]), "+f"(d[1]), "+f"(d[2]), "+f"(d[3])
                 : "r"(a[0]), "r"(a[1]), "r"(a[2]), "r"(a[3]),
                   "r"(b[0]), "r"(b[1]));
}

// ---------------------------------------------------------------------------
// Shared layout (float offsets)
// ---------------------------------------------------------------------------
#define CSTR  72
#define PST   72
#define GPSTR 66            // padded G row stride (bank-conflict avoidance)
#define OFF_GF   0          // exact G 64x64 fp32                       4096
#define OFF_GP   4096       // packed u32 bf16 hi|lo<<16, stride 66     4224
#define OFF_CROW 8320       // 2 groups x 64 x CSTR                     9216
#define OFF_BP   17536      // 2 groups x 16 x PST                      2304
#define OFF_KSH  19840      // K table                                  4096
#define OFF_INVD 23936      // 64
#define OFF_TOK  24000      // int [2 buf][4 warp][16]                   128
#define OFF_XCH  24128      // 128
#define SMEM_FLOATS 24256   // 97024 bytes

// ---------------------------------------------------------------------------
// One chunk of T (<=16) delta-rule steps for one WARP (owns 32 N-columns of
// one batch's C).  Barrier-free: only __syncwarp().
// ---------------------------------------------------------------------------
template<int T, bool TAIL, bool FIRST>
__device__ __forceinline__ void chunk(float* sm, const int* __restrict__ spq,
                                      int h, int gw, int w, int lane, int wg,
                                      int buf, int nb, int cnext,
                                      float (&D)[4][4][4])
{
    const float*    Gf   = sm + OFF_GF;
    const uint32_t* Gp   = (const uint32_t*)(sm + OFF_GP);
    const float*    invd = sm + OFF_INVD;
    float* Crow = sm + OFF_CROW + h * 64 * CSTR;
    float* Bp   = sm + OFF_BP   + h * 16 * PST;
    int*   tokw = (int*)(sm + OFF_TOK);

    const int gid = lane >> 2, tig = lane & 3;

    // tokens for this chunk (broadcast LDS, warp-own buffer)
    int s[16];
    #pragma unroll
    for (int j = 0; j < 16; j++) s[j] = tokw[buf * 64 + gw * 16 + j];

    // beta bases (C at chunk start) — own column of exported rows
    float pend[16];
    #pragma unroll
    for (int j = 0; j < 16; j++)
        pend[j] = (!FIRST && j < T) ? Crow[s[j] * CSTR + w] : 0.f;

    // prefetch next chunk's tokens (register + shared) and build the export
    // mask with a warp OR-reduction — no shared round-trip.
    uint32_t mlo, mhi;
    if (!TAIL) {
        int myntok = 0;
        if (lane < 16) {
            myntok = __ldg(spq + cnext * 16 + lane);
            tokw[nb * 64 + gw * 16 + lane] = myntok;
        }
        const uint32_t lo = (lane < 16 && myntok < 32)  ? (1u << myntok)        : 0u;
        const uint32_t hi = (lane < 16 && myntok >= 32) ? (1u << (myntok - 32)) : 0u;
        mlo = __reduce_or_sync(0xFFFFFFFFu, lo);
        mhi = __reduce_or_sync(0xFFFFFFFFu, hi);
    } else {
        mlo = 0u; mhi = 0u;
    }

    // exact serial alpha chain with forward fan-out corrections
    float alpha[16];
    #pragma unroll
    for (int u = 0; u < 16; u++) {
        if (u < T) {
            const float e = (w == s[u]) ? 1.f : 0.f;
            alpha[u] = fmaf(-invd[s[u]], pend[u], e);
            #pragma unroll
            for (int j = u + 1; j < 16; j++)
                if (j < T)
                    pend[j] = fmaf(Gf[s[u] * 64 + s[j]], alpha[u], pend[j]);
        } else alpha[u] = 0.f;
    }

    // stage B = alpha (hi/lo bf16 split), own column only
    #pragma unroll
    for (int p = 0; p < 8; p++) {
        const float x0 = alpha[2 * p], x1 = alpha[2 * p + 1];
        const __nv_bfloat16 h0 = __float2bfloat16(x0), h1 = __float2bfloat16(x1);
        const float l0 = x0 - __bfloat162float(h0), l1 = x1 - __bfloat162float(h1);
        const __nv_bfloat16 c0 = __float2bfloat16(l0), c1 = __float2bfloat16(l1);
        Bp[p * PST + w]       = __uint_as_float((uint32_t)__bfloat16_as_ushort(h0)
                              | ((uint32_t)__bfloat16_as_ushort(h1) << 16));
        Bp[(8 + p) * PST + w] = __uint_as_float((uint32_t)__bfloat16_as_ushort(c0)
                              | ((uint32_t)__bfloat16_as_ushort(c1) << 16));
    }

    __syncwarp();

    const uint64_t mask = TAIL ? (1ull << s[15])
                               : (((uint64_t)mhi << 32) | (uint64_t)mlo);

    // B fragments (own warp's columns) — reused across all 4 mi tiles
    uint32_t Bhf[4][2], Blf[4][2];
    #pragma unroll
    for (int nl = 0; nl < 4; nl++) {
        const int nc = wg * 32 + nl * 8 + gid;
        Bhf[nl][0] = __float_as_uint(Bp[tig * PST + nc]);
        Bhf[nl][1] = __float_as_uint(Bp[(tig + 4) * PST + nc]);
        Blf[nl][0] = __float_as_uint(Bp[(8 + tig) * PST + nc]);
        Blf[nl][1] = __float_as_uint(Bp[(12 + tig) * PST + nc]);
    }

    // MMA phase: A fragments gathered per-mi (short live range)
    const int ta0 = s[2 * tig]     * GPSTR;
    const int ta1 = s[2 * tig + 1] * GPSTR;
    const int ta2 = s[2 * tig + 8] * GPSTR;
    const int ta3 = s[2 * tig + 9] * GPSTR;
    #pragma unroll
    for (int mi = 0; mi < 4; mi++) {
        const int r0 = mi * 16 + gid;
        uint32_t Ahf[4], Alf[4];
        {
            const uint32_t q0 = Gp[ta0 + r0],     q1 = Gp[ta1 + r0];
            const uint32_t q2 = Gp[ta0 + r0 + 8], q3 = Gp[ta1 + r0 + 8];
            const uint32_t q4 = Gp[ta2 + r0],     q5 = Gp[ta3 + r0];
            const uint32_t q6 = Gp[ta2 + r0 + 8], q7 = Gp[ta3 + r0 + 8];
            Ahf[0] = (q0 & 0xFFFFu) | (q1 << 16);
            Alf[0] = (q0 >> 16) | (q1 & 0xFFFF0000u);
            Ahf[1] = (q2 & 0xFFFFu) | (q3 << 16);
            Alf[1] = (q2 >> 16) | (q3 & 0xFFFF0000u);
            Ahf[2] = (q4 & 0xFFFFu) | (q5 << 16);
            Alf[2] = (q4 >> 16) | (q5 & 0xFFFF0000u);
            Ahf[3] = (q6 & 0xFFFFu) | (q7 << 16);
            Alf[3] = (q6 >> 16) | (q7 & 0xFFFF0000u);
        }
        #pragma unroll
        for (int nl = 0; nl < 4; nl++) {
            mma_bf16(D[mi][nl], Ahf, Bhf[nl]);   // hh
            mma_bf16(D[mi][nl], Alf, Bhf[nl]);   // lh
            mma_bf16(D[mi][nl], Ahf, Blf[nl]);   // hl
        }
    }

    // export owned rows hit by the mask (own warp's columns)
    #pragma unroll
    for (int mi = 0; mi < 4; mi++) {
        #pragma unroll
        for (int hr = 0; hr < 2; hr++) {
            const int r = mi * 16 + hr * 8 + gid;
            if ((mask >> r) & 1ull) {
                #pragma unroll
                for (int nl = 0; nl < 4; nl++) {
                    const int cb = wg * 32 + nl * 8 + tig * 2;
                    *(float2*)&Crow[r * CSTR + cb] =
                        make_float2(D[mi][nl][2 * hr], D[mi][nl][2 * hr + 1]);
                }
            }
        }
    }
    __syncwarp();
}

// ---------------------------------------------------------------------------
// Phase 2+3: register-resident coefficient scan + readout.
// grid 128 x block 128; each of the 4 warps is a fully independent stream
// owning 32 N-columns of one batch's C.
// ---------------------------------------------------------------------------
extern __shared__ float s_dyn[];

__global__ __launch_bounds__(128, 1)
void scan_kernel(const int* __restrict__ seq,
                 const float* __restrict__ read_w,
                 const float* __restrict__ read_b,
                 const float* __restrict__ out_w,
                 const float* __restrict__ out_b,
                 float* __restrict__ out)
{
    float* sm = s_dyn;
    const int tid  = threadIdx.x;
    const int lane = tid & 31;
    const int gw   = tid >> 5;          // warp in block 0..3
    const int h    = gw >> 1;           // batch-group
    const int wg   = gw & 1;            // N-half
    const int w    = tid & 63;          // owned column
    const int b0   = blockIdx.x * 2;
    const int* spq = seq + (long)(b0 + h) * L_;

    // ---- prologue: K, invd, tokens, Gram, packed G ----
    float4* Ksh4 = (float4*)(sm + OFF_KSH);
    for (int i = tid; i < V_ * H_ / 4; i += 128)
        Ksh4[i] = reinterpret_cast<const float4*>(g_K)[i];
    if (tid < V_) sm[OFF_INVD + tid] = g_invd[tid];
    int* tokw = (int*)(sm + OFF_TOK);
    if (lane < 16) tokw[gw * 16 + lane] = __ldg(spq + lane);
    __syncthreads();

    {   // Gram: thread t computes row t>>1, 32 columns
        const int r = tid >> 1, ch = (tid & 1) * 32;
        float4 krow[16];
        #pragma unroll
        for (int i = 0; i < 16; i++) krow[i] = Ksh4[r * 16 + i];
        for (int c = ch; c < ch + 32; c++) {
            float a0 = 0.f, a1 = 0.f, a2 = 0.f, a3 = 0.f;
            #pragma unroll
            for (int i = 0; i < 16; i++) {
                const float4 kc = Ksh4[c * 16 + i];
                a0 = fmaf(krow[i].x, kc.x, a0);
                a1 = fmaf(krow[i].y, kc.y, a1);
                a2 = fmaf(krow[i].z, kc.z, a2);
                a3 = fmaf(krow[i].w, kc.w, a3);
            }
            sm[OFF_GF + r * 64 + c] = (a0 + a1) + (a2 + a3);
        }
    }
    __syncthreads();
    {   // packed bf16 hi|lo split of G, padded stride
        uint32_t* Gp = (uint32_t*)(sm + OFF_GP);
        for (int i = tid; i < V_ * V_; i += 128) {
            const int r = i >> 6, c = i & 63;
            const float g = sm[OFF_GF + i];
            const __nv_bfloat16 hi = __float2bfloat16(g);
            const __nv_bfloat16 lo = __float2bfloat16(g - __bfloat162float(hi));
            Gp[r * GPSTR + c] = (uint32_t)__bfloat16_as_ushort(hi)
                              | ((uint32_t)__bfloat16_as_ushort(lo) << 16);
        }
    }
    __syncthreads();

    float D[4][4][4];
    #pragma unroll
    for (int a = 0; a < 4; a++)
        #pragma unroll
        for (int b = 0; b < 4; b++)
            #pragma unroll
            for (int c = 0; c < 4; c++) D[a][b][c] = 0.f;

    // ---- chunk 0, then 1..254, then tail ----
    chunk<16, false, true>(sm, spq, h, gw, w, lane, wg, 0, 1, 1, D);
    #pragma unroll 1
    for (int c = 1; c < 255; c++)
        chunk<16, false, false>(sm, spq, h, gw, w, lane, wg,
                                c & 1, (c + 1) & 1, c + 1, D);
    chunk<15, true, false>(sm, spq, h, gw, w, lane, wg, 1, 0, 0, D);

    __syncthreads();

    // ---- epilogue ----
    float* xch = sm + OFF_XCH;
    const int sq = ((const int*)(sm + OFF_TOK))[64 + gw * 16 + 15];
    xch[tid] = (sm + OFF_CROW + h * 64 * CSTR)[sq * CSTR + w];
    __syncthreads();

    float ctx = 0.f;
    #pragma unroll 8
    for (int v = 0; v < V_; v++)
        ctx = fmaf(xch[(h << 6) + v], sm[OFF_KSH + v * 64 + w], ctx);
    __syncthreads(); xch[tid] = ctx; __syncthreads();

    float r = read_b[w];
    #pragma unroll 8
    for (int j = 0; j < H_; j++) r = fmaf(xch[(h << 6) + j], read_w[j * H_ + w], r);
    __syncthreads(); xch[tid] = r; __syncthreads();

    float o = out_b[w];
    #pragma unroll 8
    for (int j = 0; j < H_; j++) o = fmaf(xch[(h << 6) + j], out_w[j * V_ + w], o);
    out[(b0 + h) * V_ + w] = o;
}

// ---------------------------------------------------------------------------
extern "C" void kernel_launch(void* const* d_in, const int* in_sizes, int n_in,
                              void* d_out, int out_size)
{
    const int*   seq     = (const int*)  d_in[0];
    const float* embed_W = (const float*)d_in[1];
    const float* ff_w1   = (const float*)d_in[2];
    const float* ff_b1   = (const float*)d_in[3];
    const float* ff_w2   = (const float*)d_in[4];
    const float* ff_b2   = (const float*)d_in[5];
    const float* ln_w    = (const float*)d_in[6];
    const float* ln_b    = (const float*)d_in[7];
    const float* read_w  = (const float*)d_in[8];
    const float* read_b  = (const float*)d_in[9];
    const float* out_w   = (const float*)d_in[10];
    const float* out_b   = (const float*)d_in[11];
    float* out = (float*)d_out;

    const int smem_bytes = SMEM_FLOATS * 4;
    cudaFuncSetAttribute(scan_kernel,
                         cudaFuncAttributeMaxDynamicSharedMemorySize, smem_bytes);

    build_table_kernel<<<V_, H_>>>(embed_W, ff_w1, ff_b1, ff_w2, ff_b2,
                                   ln_w, ln_b);
    scan_kernel<<<B_ / 2, 128, smem_bytes>>>(seq, read_w, read_b,
                                             out_w, out_b, out);
}